// round 2
// baseline (speedup 1.0000x reference)
#include <cuda_runtime.h>
#include <cuda_bf16.h>

#define N_NODES 100000
#define N_EDGES 800000
#define F 128
#define HID 128

// Precomputed per-node tables: A = h @ W1[0:128,:] + b1,  B = h @ W1[128:256,:]
// 2 * 100000 * 128 * 4 bytes = 102.4 MB static device scratch (allowed).
__device__ float d_AB[2u * N_NODES * F];

// ---------------------------------------------------------------------------
// Kernel 1: node GEMM.  grid.y = part (0 -> A with b1, 1 -> B).
// Tile: BM=64 nodes x BN=128 cols, K=128. 256 threads, each 4x8 outputs.
// ---------------------------------------------------------------------------
__global__ void node_kernel(const float* __restrict__ h,
                            const float* __restrict__ W1,
                            const float* __restrict__ b1) {
    extern __shared__ float sm[];
    float* h_s = sm;              // 64*128 floats = 32 KB
    float* w_s = sm + 64 * 128;   // 128*128 floats = 64 KB
    const int tid  = threadIdx.x;
    const int part = blockIdx.y;
    const int m0   = blockIdx.x * 64;

    // Load weight slice (W1 rows part*128 .. part*128+127), row-major [k][n]
    const float4* W4 = (const float4*)(W1 + part * F * HID);
    float4* w_s4 = (float4*)w_s;
    #pragma unroll
    for (int i = tid; i < 128 * 32; i += 256) w_s4[i] = W4[i];

    // Load h tile (guard tail rows)
    const float4* h4 = (const float4*)h;
    float4* h_s4 = (float4*)h_s;
    #pragma unroll
    for (int i = tid; i < 64 * 32; i += 256) {
        int row = i >> 5, v = i & 31;
        int r = m0 + row;
        float4 val = make_float4(0.f, 0.f, 0.f, 0.f);
        if (r < N_NODES) val = h4[(size_t)r * 32 + v];
        h_s4[i] = val;
    }
    __syncthreads();

    const int tc = tid & 15, tr = tid >> 4;
    float acc[4][8];
    #pragma unroll
    for (int i = 0; i < 4; i++)
        #pragma unroll
        for (int j = 0; j < 8; j++) acc[i][j] = 0.f;

    #pragma unroll 4
    for (int k = 0; k < 128; k++) {
        float a[4];
        #pragma unroll
        for (int i = 0; i < 4; i++) a[i] = h_s[(tr * 4 + i) * 128 + k];
        float4 b0 = w_s4[k * 32 + tc * 2];
        float4 b1v = w_s4[k * 32 + tc * 2 + 1];
        float b[8] = {b0.x, b0.y, b0.z, b0.w, b1v.x, b1v.y, b1v.z, b1v.w};
        #pragma unroll
        for (int i = 0; i < 4; i++)
            #pragma unroll
            for (int j = 0; j < 8; j++)
                acc[i][j] = fmaf(a[i], b[j], acc[i][j]);
    }

    float bias[8];
    #pragma unroll
    for (int j = 0; j < 8; j++) bias[j] = (part == 0) ? b1[tc * 8 + j] : 0.f;

    float* dstp = d_AB + (size_t)part * N_NODES * F;
    #pragma unroll
    for (int i = 0; i < 4; i++) {
        int r = m0 + tr * 4 + i;
        if (r < N_NODES) {
            float4 v0, v1;
            v0.x = acc[i][0] + bias[0]; v0.y = acc[i][1] + bias[1];
            v0.z = acc[i][2] + bias[2]; v0.w = acc[i][3] + bias[3];
            v1.x = acc[i][4] + bias[4]; v1.y = acc[i][5] + bias[5];
            v1.z = acc[i][6] + bias[6]; v1.w = acc[i][7] + bias[7];
            float4* p = (float4*)(dstp + (size_t)r * 128 + tc * 8);
            p[0] = v0;
            p[1] = v1;
        }
    }
}

// ---------------------------------------------------------------------------
// Kernel 2: per-edge fused gather + relu + layer2 GEMM + layer3.
// Tile: 128 edges x 128 hidden, K=128. 256 threads, each 8x8 outputs.
// Indices are int32 (JAX x64 disabled: "int64" inputs are int32 on device).
// ---------------------------------------------------------------------------
__global__ void edge_kernel(const int* __restrict__ src,
                            const int* __restrict__ dst,
                            const float* __restrict__ W2,
                            const float* __restrict__ b2,
                            const float* __restrict__ W3,
                            const float* __restrict__ b3,
                            float* __restrict__ out) {
    extern __shared__ float sm[];
    float* x1_s = sm;               // 128*128 floats = 64 KB
    float* w2_s = sm + 128 * 128;   // 128*128 floats = 64 KB
    __shared__ int   s_src[128];
    __shared__ int   s_dst[128];
    __shared__ float s_w3[256];
    __shared__ float s_out[256];

    const int tid = threadIdx.x;
    const int e0  = blockIdx.x * 128;

    if (tid < 128) s_src[tid] = src[e0 + tid];
    else           s_dst[tid - 128] = dst[e0 + tid - 128];
    s_w3[tid]  = W3[tid];        // W3 is 128x2 = 256 floats
    s_out[tid] = b3[tid & 1];    // init partial-sum buffer with bias

    float4* w2_s4 = (float4*)w2_s;
    const float4* W2_4 = (const float4*)W2;
    #pragma unroll
    for (int i = tid; i < 128 * 32; i += 256) w2_s4[i] = W2_4[i];
    __syncthreads();

    // Gather A[src] + B[dst], relu, into x1 tile
    const float4* A4 = (const float4*)d_AB;
    const float4* B4 = (const float4*)(d_AB + (size_t)N_NODES * F);
    float4* x1_s4 = (float4*)x1_s;
    #pragma unroll
    for (int i = 0; i < 16; i++) {
        int lin = tid + 256 * i;
        int e = lin >> 5, v = lin & 31;
        float4 a = A4[(size_t)s_src[e] * 32 + v];
        float4 b = B4[(size_t)s_dst[e] * 32 + v];
        float4 r;
        r.x = fmaxf(a.x + b.x, 0.f);
        r.y = fmaxf(a.y + b.y, 0.f);
        r.z = fmaxf(a.z + b.z, 0.f);
        r.w = fmaxf(a.w + b.w, 0.f);
        x1_s4[lin] = r;
    }
    __syncthreads();

    const int tc = tid & 15, tr = tid >> 4;
    float acc[8][8];
    #pragma unroll
    for (int i = 0; i < 8; i++)
        #pragma unroll
        for (int j = 0; j < 8; j++) acc[i][j] = 0.f;

    #pragma unroll 4
    for (int k = 0; k < 128; k++) {
        float a[8];
        #pragma unroll
        for (int i = 0; i < 8; i++) a[i] = x1_s[(tr * 8 + i) * 128 + k];
        float4 b0 = w2_s4[k * 32 + tc * 2];
        float4 b1v = w2_s4[k * 32 + tc * 2 + 1];
        float b[8] = {b0.x, b0.y, b0.z, b0.w, b1v.x, b1v.y, b1v.z, b1v.w};
        #pragma unroll
        for (int i = 0; i < 8; i++)
            #pragma unroll
            for (int j = 0; j < 8; j++)
                acc[i][j] = fmaf(a[i], b[j], acc[i][j]);
    }

    // bias2 + relu + layer3 partial reduction
    float4 b2a = ((const float4*)b2)[tc * 2];
    float4 b2b = ((const float4*)b2)[tc * 2 + 1];
    float b2r[8] = {b2a.x, b2a.y, b2a.z, b2a.w, b2b.x, b2b.y, b2b.z, b2b.w};
    float w30[8], w31[8];
    #pragma unroll
    for (int j = 0; j < 8; j++) {
        w30[j] = s_w3[(tc * 8 + j) * 2];
        w31[j] = s_w3[(tc * 8 + j) * 2 + 1];
    }
    #pragma unroll
    for (int i = 0; i < 8; i++) {
        float p0 = 0.f, p1 = 0.f;
        #pragma unroll
        for (int j = 0; j < 8; j++) {
            float x = fmaxf(acc[i][j] + b2r[j], 0.f);
            p0 = fmaf(x, w30[j], p0);
            p1 = fmaf(x, w31[j], p1);
        }
        atomicAdd(&s_out[(tr * 8 + i) * 2], p0);
        atomicAdd(&s_out[(tr * 8 + i) * 2 + 1], p1);
    }
    __syncthreads();

    out[(size_t)e0 * 2 + tid] = s_out[tid];   // 128 edges x 2, coalesced
}

// ---------------------------------------------------------------------------
extern "C" void kernel_launch(void* const* d_in, const int* in_sizes, int n_in,
                              void* d_out, int out_size) {
    const float* h   = (const float*)d_in[0];
    const int*   src = (const int*)d_in[1];
    const int*   dst = (const int*)d_in[2];
    const float* W1  = (const float*)d_in[3];
    const float* b1  = (const float*)d_in[4];
    const float* W2  = (const float*)d_in[5];
    const float* b2  = (const float*)d_in[6];
    const float* W3  = (const float*)d_in[7];
    const float* b3  = (const float*)d_in[8];
    float* out = (float*)d_out;

    cudaFuncSetAttribute(node_kernel, cudaFuncAttributeMaxDynamicSharedMemorySize, 98304);
    cudaFuncSetAttribute(edge_kernel, cudaFuncAttributeMaxDynamicSharedMemorySize, 131072);

    dim3 g1((N_NODES + 63) / 64, 2);
    node_kernel<<<g1, 256, 98304>>>(h, W1, b1);
    edge_kernel<<<N_EDGES / 128, 256, 131072>>>(src, dst, W2, b2, W3, b3, out);
}

// round 3
// speedup vs baseline: 1.9136x; 1.9136x over previous
#include <cuda_runtime.h>
#include <cuda_bf16.h>
#include <cstdint>

#define N_NODES 100000
#define N_EDGES 800000
#define F 128
#define HID 128
#define PITCH 136   // bf16 elements per row in shared tiles (conflict-free for mma frag loads)

// Precomputed per-node tables: A = h @ W1[0:128,:] + b1,  B = h @ W1[128:256,:]
__device__ float d_AB[2u * N_NODES * F];

// ---------------------------------------------------------------------------
// Kernel 1: node GEMM (unchanged from R2 — fp32 SIMT).
// ---------------------------------------------------------------------------
__global__ void node_kernel(const float* __restrict__ h,
                            const float* __restrict__ W1,
                            const float* __restrict__ b1) {
    extern __shared__ float sm[];
    float* h_s = sm;              // 64*128
    float* w_s = sm + 64 * 128;   // 128*128
    const int tid  = threadIdx.x;
    const int part = blockIdx.y;
    const int m0   = blockIdx.x * 64;

    const float4* W4 = (const float4*)(W1 + part * F * HID);
    float4* w_s4 = (float4*)w_s;
    #pragma unroll
    for (int i = tid; i < 128 * 32; i += 256) w_s4[i] = W4[i];

    const float4* h4 = (const float4*)h;
    float4* h_s4 = (float4*)h_s;
    #pragma unroll
    for (int i = tid; i < 64 * 32; i += 256) {
        int row = i >> 5, v = i & 31;
        int r = m0 + row;
        float4 val = make_float4(0.f, 0.f, 0.f, 0.f);
        if (r < N_NODES) val = h4[(size_t)r * 32 + v];
        h_s4[i] = val;
    }
    __syncthreads();

    const int tc = tid & 15, tr = tid >> 4;
    float acc[4][8];
    #pragma unroll
    for (int i = 0; i < 4; i++)
        #pragma unroll
        for (int j = 0; j < 8; j++) acc[i][j] = 0.f;

    #pragma unroll 4
    for (int k = 0; k < 128; k++) {
        float a[4];
        #pragma unroll
        for (int i = 0; i < 4; i++) a[i] = h_s[(tr * 4 + i) * 128 + k];
        float4 b0 = w_s4[k * 32 + tc * 2];
        float4 b1v = w_s4[k * 32 + tc * 2 + 1];
        float b[8] = {b0.x, b0.y, b0.z, b0.w, b1v.x, b1v.y, b1v.z, b1v.w};
        #pragma unroll
        for (int i = 0; i < 4; i++)
            #pragma unroll
            for (int j = 0; j < 8; j++)
                acc[i][j] = fmaf(a[i], b[j], acc[i][j]);
    }

    float bias[8];
    #pragma unroll
    for (int j = 0; j < 8; j++) bias[j] = (part == 0) ? b1[tc * 8 + j] : 0.f;

    float* dstp = d_AB + (size_t)part * N_NODES * F;
    #pragma unroll
    for (int i = 0; i < 4; i++) {
        int r = m0 + tr * 4 + i;
        if (r < N_NODES) {
            float4 v0, v1;
            v0.x = acc[i][0] + bias[0]; v0.y = acc[i][1] + bias[1];
            v0.z = acc[i][2] + bias[2]; v0.w = acc[i][3] + bias[3];
            v1.x = acc[i][4] + bias[4]; v1.y = acc[i][5] + bias[5];
            v1.z = acc[i][6] + bias[6]; v1.w = acc[i][7] + bias[7];
            float4* p = (float4*)(dstp + (size_t)r * 128 + tc * 8);
            p[0] = v0;
            p[1] = v1;
        }
    }
}

// ---------------------------------------------------------------------------
// bf16 mma helper: D = A(16x16,row) * B(16x8,col) + D, fp32 accum.
// ---------------------------------------------------------------------------
__device__ __forceinline__ void mma_bf16(float* c, const uint32_t* a, const uint32_t* b) {
    asm volatile(
        "mma.sync.aligned.m16n8k16.row.col.f32.bf16.bf16.f32 "
        "{%0,%1,%2,%3}, {%4,%5,%6,%7}, {%8,%9}, {%0,%1,%2,%3};\n"
        : "+f"(c[0]), "+f"(c[1]), "+f"(c[2]), "+f"(c[3])
        : "r"(a[0]), "r"(a[1]), "r"(a[2]), "r"(a[3]), "r"(b[0]), "r"(b[1]));
}

__device__ __forceinline__ void split_bf16(float x, __nv_bfloat16& hi, __nv_bfloat16& lo) {
    hi = __float2bfloat16(x);
    lo = __float2bfloat16(x - __bfloat162float(hi));
}

// ---------------------------------------------------------------------------
// Kernel 2: per-edge fused gather + relu + layer2 tensor-core GEMM + layer3.
// Tile: 128 edges x 128 hidden, K=128. 256 threads = 8 warps (4 M-blocks x 2 N-blocks).
// 3-pass bf16 split GEMM on tensor cores, fp32 accumulate.
// ---------------------------------------------------------------------------
__global__ void edge_kernel(const int* __restrict__ src,
                            const int* __restrict__ dst,
                            const float* __restrict__ W2,
                            const float* __restrict__ b2,
                            const float* __restrict__ W3,
                            const float* __restrict__ b3,
                            float* __restrict__ out) {
    extern __shared__ __nv_bfloat16 smb[];
    __nv_bfloat16* x_hi = smb;                    // [128][PITCH]
    __nv_bfloat16* x_lo = smb + 128 * PITCH;
    __nv_bfloat16* w_hi = smb + 2 * 128 * PITCH;  // transposed: [n][k]
    __nv_bfloat16* w_lo = smb + 3 * 128 * PITCH;

    __shared__ int   s_src[128];
    __shared__ int   s_dst[128];
    __shared__ float s_b2[128];
    __shared__ float s_w3[256];
    __shared__ float s_out[256];

    const int tid  = threadIdx.x;
    const int e0   = blockIdx.x * 128;
    const int warp = tid >> 5;
    const int lane = tid & 31;
    const int g    = lane >> 2;       // group id (0..7)
    const int tig  = lane & 3;        // thread in group
    const int wm   = warp & 3;        // M block (32 rows)
    const int wn   = warp >> 2;       // N block (64 cols)

    if (tid < 128) { s_src[tid] = src[e0 + tid]; s_b2[tid] = b2[tid]; }
    else           { s_dst[tid - 128] = dst[e0 + tid - 128]; }
    s_w3[tid]  = W3[tid];
    s_out[tid] = b3[tid & 1];

    // W2 [k][n] -> transposed split tiles w_hi/w_lo [n][k]
    #pragma unroll
    for (int j = 0; j < 64; j++) {
        int idx = tid + 256 * j;
        int k = idx >> 7, n = idx & 127;
        float w = W2[idx];
        __nv_bfloat16 wh, wl;
        split_bf16(w, wh, wl);
        w_hi[n * PITCH + k] = wh;
        w_lo[n * PITCH + k] = wl;
    }
    __syncthreads();

    // Gather A[src] + B[dst], relu, split into bf16 hi/lo tiles [e][k]
    const float4* A4 = (const float4*)d_AB;
    const float4* B4 = (const float4*)(d_AB + (size_t)N_NODES * F);
    #pragma unroll
    for (int i = 0; i < 16; i++) {
        int lin = tid + 256 * i;
        int e = lin >> 5, v = lin & 31;
        float4 a = A4[(size_t)s_src[e] * 32 + v];
        float4 b = B4[(size_t)s_dst[e] * 32 + v];
        float r0 = fmaxf(a.x + b.x, 0.f), r1 = fmaxf(a.y + b.y, 0.f);
        float r2 = fmaxf(a.z + b.z, 0.f), r3 = fmaxf(a.w + b.w, 0.f);
        __nv_bfloat16 h0, h1, h2, h3, l0, l1, l2, l3;
        split_bf16(r0, h0, l0); split_bf16(r1, h1, l1);
        split_bf16(r2, h2, l2); split_bf16(r3, h3, l3);
        int base = e * PITCH + v * 4;
        *(__nv_bfloat162*)&x_hi[base]     = __halves2bfloat162(h0, h1);
        *(__nv_bfloat162*)&x_hi[base + 2] = __halves2bfloat162(h2, h3);
        *(__nv_bfloat162*)&x_lo[base]     = __halves2bfloat162(l0, l1);
        *(__nv_bfloat162*)&x_lo[base + 2] = __halves2bfloat162(l2, l3);
    }
    __syncthreads();

    // Main loop: D[128x128] = x1 @ W2 via 3-pass bf16 split
    float acc[2][8][4];
    #pragma unroll
    for (int mt = 0; mt < 2; mt++)
        #pragma unroll
        for (int nt = 0; nt < 8; nt++)
            #pragma unroll
            for (int q = 0; q < 4; q++) acc[mt][nt][q] = 0.f;

    #pragma unroll
    for (int ks = 0; ks < 8; ks++) {
        const int ka = ks * 16 + 2 * tig;

        uint32_t a_hi[2][4], a_lo[2][4];
        #pragma unroll
        for (int mt = 0; mt < 2; mt++) {
            int m = wm * 32 + mt * 16 + g;
            const __nv_bfloat16* ph = &x_hi[m * PITCH + ka];
            const __nv_bfloat16* pl = &x_lo[m * PITCH + ka];
            a_hi[mt][0] = *(const uint32_t*)ph;
            a_hi[mt][1] = *(const uint32_t*)(ph + 8 * PITCH);
            a_hi[mt][2] = *(const uint32_t*)(ph + 8);
            a_hi[mt][3] = *(const uint32_t*)(ph + 8 * PITCH + 8);
            a_lo[mt][0] = *(const uint32_t*)pl;
            a_lo[mt][1] = *(const uint32_t*)(pl + 8 * PITCH);
            a_lo[mt][2] = *(const uint32_t*)(pl + 8);
            a_lo[mt][3] = *(const uint32_t*)(pl + 8 * PITCH + 8);
        }

        uint32_t b_hi[8][2], b_lo[8][2];
        #pragma unroll
        for (int nt = 0; nt < 8; nt++) {
            int n = wn * 64 + nt * 8 + g;
            const __nv_bfloat16* pw = &w_hi[n * PITCH + ka];
            const __nv_bfloat16* pv = &w_lo[n * PITCH + ka];
            b_hi[nt][0] = *(const uint32_t*)pw;
            b_hi[nt][1] = *(const uint32_t*)(pw + 8);
            b_lo[nt][0] = *(const uint32_t*)pv;
            b_lo[nt][1] = *(const uint32_t*)(pv + 8);
        }

        #pragma unroll
        for (int mt = 0; mt < 2; mt++)
            #pragma unroll
            for (int nt = 0; nt < 8; nt++) {
                mma_bf16(acc[mt][nt], a_hi[mt], b_hi[nt]);
                mma_bf16(acc[mt][nt], a_hi[mt], b_lo[nt]);
                mma_bf16(acc[mt][nt], a_lo[mt], b_hi[nt]);
            }
    }

    // Epilogue: bias2 + relu + layer3 partial products, reduce within lane group
    float p[2][2][2];   // [mt][row(0/+8)][out]
    #pragma unroll
    for (int mt = 0; mt < 2; mt++)
        #pragma unroll
        for (int r = 0; r < 2; r++) { p[mt][r][0] = 0.f; p[mt][r][1] = 0.f; }

    #pragma unroll
    for (int nt = 0; nt < 8; nt++) {
        int c0 = wn * 64 + nt * 8 + 2 * tig;
        float bb0 = s_b2[c0], bb1 = s_b2[c0 + 1];
        float w300 = s_w3[c0 * 2],       w310 = s_w3[c0 * 2 + 1];
        float w301 = s_w3[(c0 + 1) * 2], w311 = s_w3[(c0 + 1) * 2 + 1];
        #pragma unroll
        for (int mt = 0; mt < 2; mt++) {
            float x00 = fmaxf(acc[mt][nt][0] + bb0, 0.f);
            float x01 = fmaxf(acc[mt][nt][1] + bb1, 0.f);
            float x10 = fmaxf(acc[mt][nt][2] + bb0, 0.f);
            float x11 = fmaxf(acc[mt][nt][3] + bb1, 0.f);
            p[mt][0][0] = fmaf(x00, w300, fmaf(x01, w301, p[mt][0][0]));
            p[mt][0][1] = fmaf(x00, w310, fmaf(x01, w311, p[mt][0][1]));
            p[mt][1][0] = fmaf(x10, w300, fmaf(x11, w301, p[mt][1][0]));
            p[mt][1][1] = fmaf(x10, w310, fmaf(x11, w311, p[mt][1][1]));
        }
    }

    #pragma unroll
    for (int mt = 0; mt < 2; mt++)
        #pragma unroll
        for (int r = 0; r < 2; r++)
            #pragma unroll
            for (int o = 0; o < 2; o++) {
                float v = p[mt][r][o];
                v += __shfl_xor_sync(0xffffffffu, v, 1);
                v += __shfl_xor_sync(0xffffffffu, v, 2);
                p[mt][r][o] = v;
            }

    if (tig == 0) {
        #pragma unroll
        for (int mt = 0; mt < 2; mt++) {
            int r0 = wm * 32 + mt * 16 + g;
            atomicAdd(&s_out[r0 * 2],            p[mt][0][0]);
            atomicAdd(&s_out[r0 * 2 + 1],        p[mt][0][1]);
            atomicAdd(&s_out[(r0 + 8) * 2],      p[mt][1][0]);
            atomicAdd(&s_out[(r0 + 8) * 2 + 1],  p[mt][1][1]);
        }
    }
    __syncthreads();

    out[(size_t)e0 * 2 + tid] = s_out[tid];
}

// ---------------------------------------------------------------------------
extern "C" void kernel_launch(void* const* d_in, const int* in_sizes, int n_in,
                              void* d_out, int out_size) {
    const float* h   = (const float*)d_in[0];
    const int*   src = (const int*)d_in[1];
    const int*   dst = (const int*)d_in[2];
    const float* W1  = (const float*)d_in[3];
    const float* b1  = (const float*)d_in[4];
    const float* W2  = (const float*)d_in[5];
    const float* b2  = (const float*)d_in[6];
    const float* W3  = (const float*)d_in[7];
    const float* b3  = (const float*)d_in[8];
    float* out = (float*)d_out;

    const int edge_smem = 4 * 128 * PITCH * (int)sizeof(__nv_bfloat16);  // 139264
    cudaFuncSetAttribute(node_kernel, cudaFuncAttributeMaxDynamicSharedMemorySize, 98304);
    cudaFuncSetAttribute(edge_kernel, cudaFuncAttributeMaxDynamicSharedMemorySize, edge_smem);

    dim3 g1((N_NODES + 63) / 64, 2);
    node_kernel<<<g1, 256, 98304>>>(h, W1, b1);
    edge_kernel<<<N_EDGES / 128, 256, edge_smem>>>(src, dst, W2, b2, W3, b3, out);
}

// round 4
// speedup vs baseline: 3.2708x; 1.7092x over previous
#include <cuda_runtime.h>
#include <cuda_bf16.h>
#include <cstdint>

#define N_NODES 100000
#define N_EDGES 800000
#define F 128
#define HID 128
#define PITCH 136            // bf16 per row in shared tiles (conflict-free frag loads)
#define TSZ (128 * PITCH)    // one 128-row tile in bf16 elems
#define TILES (N_EDGES / 128)
#define EDGE_GRID 148

// Precomputed per-node tables: A = h @ W1[0:128,:] + b1,  B = h @ W1[128:256,:]
__device__ float d_AB[2u * N_NODES * F];

// ---------------------------------------------------------------------------
// Kernel 1: node GEMM (fp32 SIMT, unchanged).
// ---------------------------------------------------------------------------
__global__ void node_kernel(const float* __restrict__ h,
                            const float* __restrict__ W1,
                            const float* __restrict__ b1) {
    extern __shared__ float sm[];
    float* h_s = sm;
    float* w_s = sm + 64 * 128;
    const int tid  = threadIdx.x;
    const int part = blockIdx.y;
    const int m0   = blockIdx.x * 64;

    const float4* W4 = (const float4*)(W1 + part * F * HID);
    float4* w_s4 = (float4*)w_s;
    #pragma unroll
    for (int i = tid; i < 128 * 32; i += 256) w_s4[i] = W4[i];

    const float4* h4 = (const float4*)h;
    float4* h_s4 = (float4*)h_s;
    #pragma unroll
    for (int i = tid; i < 64 * 32; i += 256) {
        int row = i >> 5, v = i & 31;
        int r = m0 + row;
        float4 val = make_float4(0.f, 0.f, 0.f, 0.f);
        if (r < N_NODES) val = h4[(size_t)r * 32 + v];
        h_s4[i] = val;
    }
    __syncthreads();

    const int tc = tid & 15, tr = tid >> 4;
    float acc[4][8];
    #pragma unroll
    for (int i = 0; i < 4; i++)
        #pragma unroll
        for (int j = 0; j < 8; j++) acc[i][j] = 0.f;

    #pragma unroll 4
    for (int k = 0; k < 128; k++) {
        float a[4];
        #pragma unroll
        for (int i = 0; i < 4; i++) a[i] = h_s[(tr * 4 + i) * 128 + k];
        float4 b0 = w_s4[k * 32 + tc * 2];
        float4 b1v = w_s4[k * 32 + tc * 2 + 1];
        float b[8] = {b0.x, b0.y, b0.z, b0.w, b1v.x, b1v.y, b1v.z, b1v.w};
        #pragma unroll
        for (int i = 0; i < 4; i++)
            #pragma unroll
            for (int j = 0; j < 8; j++)
                acc[i][j] = fmaf(a[i], b[j], acc[i][j]);
    }

    float bias[8];
    #pragma unroll
    for (int j = 0; j < 8; j++) bias[j] = (part == 0) ? b1[tc * 8 + j] : 0.f;

    float* dstp = d_AB + (size_t)part * N_NODES * F;
    #pragma unroll
    for (int i = 0; i < 4; i++) {
        int r = m0 + tr * 4 + i;
        if (r < N_NODES) {
            float4 v0, v1;
            v0.x = acc[i][0] + bias[0]; v0.y = acc[i][1] + bias[1];
            v0.z = acc[i][2] + bias[2]; v0.w = acc[i][3] + bias[3];
            v1.x = acc[i][4] + bias[4]; v1.y = acc[i][5] + bias[5];
            v1.z = acc[i][6] + bias[6]; v1.w = acc[i][7] + bias[7];
            float4* p = (float4*)(dstp + (size_t)r * 128 + tc * 8);
            p[0] = v0;
            p[1] = v1;
        }
    }
}

// ---------------------------------------------------------------------------
__device__ __forceinline__ void mma_bf16(float* c, const uint32_t* a, const uint32_t* b) {
    asm volatile(
        "mma.sync.aligned.m16n8k16.row.col.f32.bf16.bf16.f32 "
        "{%0,%1,%2,%3}, {%4,%5,%6,%7}, {%8,%9}, {%0,%1,%2,%3};\n"
        : "+f"(c[0]), "+f"(c[1]), "+f"(c[2]), "+f"(c[3])
        : "r"(a[0]), "r"(a[1]), "r"(a[2]), "r"(a[3]), "r"(b[0]), "r"(b[1]));
}

__device__ __forceinline__ void split_bf16(float x, __nv_bfloat16& hi, __nv_bfloat16& lo) {
    hi = __float2bfloat16(x);
    lo = __float2bfloat16(x - __bfloat162float(hi));
}

__device__ __forceinline__ uint32_t pack2(__nv_bfloat16 a, __nv_bfloat16 b) {
    __nv_bfloat162 t = __halves2bfloat162(a, b);
    return *(uint32_t*)&t;
}

// ---------------------------------------------------------------------------
// Kernel 2: persistent, warp-specialized edge kernel.
// 384 threads: warps 0-7 MMA consumers, warps 8-11 producers (gather+split).
// Double-buffered x tile; W2 split loaded once per CTA.
// ---------------------------------------------------------------------------
__global__ void __launch_bounds__(384, 1)
edge_kernel(const int* __restrict__ src,
            const int* __restrict__ dst,
            const float* __restrict__ W2,
            const float* __restrict__ b2,
            const float* __restrict__ W3,
            const float* __restrict__ b3,
            float* __restrict__ out) {
    extern __shared__ __nv_bfloat16 smb[];
    __nv_bfloat16* w_hi = smb;                 // [n][k] transposed
    __nv_bfloat16* w_lo = smb + TSZ;
    __nv_bfloat16* xbuf = smb + 2 * TSZ;       // 4 tiles: buf0{hi,lo}, buf1{hi,lo}

    __shared__ float s_b2[128];
    __shared__ float s_w3[256];
    __shared__ float s_b3[2];
    __shared__ float s_part[2][128][2];        // [wn][row][out]

    const int tid  = threadIdx.x;
    const int lane = tid & 31;

    // ---- one-time: W2 split (transposed), small params ----
    for (int idx = tid; idx < 128 * 128; idx += 384) {
        int k = idx >> 7, n = idx & 127;
        float w = W2[idx];
        __nv_bfloat16 wh, wl;
        split_bf16(w, wh, wl);
        w_hi[n * PITCH + k] = wh;
        w_lo[n * PITCH + k] = wl;
    }
    if (tid < 128) s_b2[tid] = b2[tid];
    if (tid < 256) s_w3[tid] = W3[tid];
    if (tid < 2)   s_b3[tid] = b3[tid];
    __syncthreads();

    const float4* A4 = (const float4*)d_AB;
    const float4* B4 = (const float4*)(d_AB + (size_t)N_NODES * F);
    const bool is_consumer = tid < 256;
    const int  ptid = tid - 256;               // producer thread id 0..127

    // producer fill: gather + relu + split into buffer `buf` for tile `t`
    auto fill = [&](int buf, int t) {
        __nv_bfloat16* xh = xbuf + (2 * buf) * TSZ;
        __nv_bfloat16* xl = xbuf + (2 * buf + 1) * TSZ;
        const int e0 = t * 128;
        #pragma unroll
        for (int i = 0; i < 32; i++) {
            int lin = ptid + 128 * i;
            int e = lin >> 5, v = lin & 31;     // e uniform per producer warp
            int si = src[e0 + e], di = dst[e0 + e];
            float4 a = A4[(size_t)si * 32 + v];
            float4 b = B4[(size_t)di * 32 + v];
            float r0 = fmaxf(a.x + b.x, 0.f), r1 = fmaxf(a.y + b.y, 0.f);
            float r2 = fmaxf(a.z + b.z, 0.f), r3 = fmaxf(a.w + b.w, 0.f);
            __nv_bfloat16 h0, h1, h2, h3, l0, l1, l2, l3;
            split_bf16(r0, h0, l0); split_bf16(r1, h1, l1);
            split_bf16(r2, h2, l2); split_bf16(r3, h3, l3);
            int base = e * PITCH + v * 4;
            uint2 vh = make_uint2(pack2(h0, h1), pack2(h2, h3));
            uint2 vl = make_uint2(pack2(l0, l1), pack2(l2, l3));
            *(uint2*)&xh[base] = vh;
            *(uint2*)&xl[base] = vl;
        }
    };

    // ---- prologue: fill buffer 0 with first tile ----
    if (!is_consumer) fill(0, blockIdx.x);
    __syncthreads();

    const int warp = tid >> 5;
    const int g    = lane >> 2;
    const int tig  = lane & 3;
    const int wm   = warp & 3;
    const int wn   = warp >> 2;    // valid for consumer warps only

    int s = 0;
    for (int t = blockIdx.x; t < TILES; t += EDGE_GRID, s++) {
        const int buf = s & 1;
        if (is_consumer) {
            const __nv_bfloat16* xh = xbuf + (2 * buf) * TSZ;
            const __nv_bfloat16* xl = xbuf + (2 * buf + 1) * TSZ;

            float acc[2][8][4];
            #pragma unroll
            for (int mt = 0; mt < 2; mt++)
                #pragma unroll
                for (int nt = 0; nt < 8; nt++)
                    #pragma unroll
                    for (int q = 0; q < 4; q++) acc[mt][nt][q] = 0.f;

            #pragma unroll
            for (int ks = 0; ks < 8; ks++) {
                const int ka = ks * 16 + 2 * tig;

                uint32_t a_hi[2][4], a_lo[2][4];
                #pragma unroll
                for (int mt = 0; mt < 2; mt++) {
                    int m = wm * 32 + mt * 16 + g;
                    const __nv_bfloat16* ph = &xh[m * PITCH + ka];
                    const __nv_bfloat16* pl = &xl[m * PITCH + ka];
                    a_hi[mt][0] = *(const uint32_t*)ph;
                    a_hi[mt][1] = *(const uint32_t*)(ph + 8 * PITCH);
                    a_hi[mt][2] = *(const uint32_t*)(ph + 8);
                    a_hi[mt][3] = *(const uint32_t*)(ph + 8 * PITCH + 8);
                    a_lo[mt][0] = *(const uint32_t*)pl;
                    a_lo[mt][1] = *(const uint32_t*)(pl + 8 * PITCH);
                    a_lo[mt][2] = *(const uint32_t*)(pl + 8);
                    a_lo[mt][3] = *(const uint32_t*)(pl + 8 * PITCH + 8);
                }

                uint32_t b_hi[8][2], b_lo[8][2];
                #pragma unroll
                for (int nt = 0; nt < 8; nt++) {
                    int n = wn * 64 + nt * 8 + g;
                    const __nv_bfloat16* pw = &w_hi[n * PITCH + ka];
                    const __nv_bfloat16* pv = &w_lo[n * PITCH + ka];
                    b_hi[nt][0] = *(const uint32_t*)pw;
                    b_hi[nt][1] = *(const uint32_t*)(pw + 8);
                    b_lo[nt][0] = *(const uint32_t*)pv;
                    b_lo[nt][1] = *(const uint32_t*)(pv + 8);
                }

                #pragma unroll
                for (int mt = 0; mt < 2; mt++)
                    #pragma unroll
                    for (int nt = 0; nt < 8; nt++) {
                        mma_bf16(acc[mt][nt], a_hi[mt], b_hi[nt]);
                        mma_bf16(acc[mt][nt], a_hi[mt], b_lo[nt]);
                        mma_bf16(acc[mt][nt], a_lo[mt], b_hi[nt]);
                    }
            }

            // epilogue: bias2 + relu + layer3 partials
            float p[2][2][2];
            #pragma unroll
            for (int mt = 0; mt < 2; mt++)
                #pragma unroll
                for (int r = 0; r < 2; r++) { p[mt][r][0] = 0.f; p[mt][r][1] = 0.f; }

            #pragma unroll
            for (int nt = 0; nt < 8; nt++) {
                int c0 = wn * 64 + nt * 8 + 2 * tig;
                float bb0 = s_b2[c0], bb1 = s_b2[c0 + 1];
                float w300 = s_w3[c0 * 2],       w310 = s_w3[c0 * 2 + 1];
                float w301 = s_w3[(c0 + 1) * 2], w311 = s_w3[(c0 + 1) * 2 + 1];
                #pragma unroll
                for (int mt = 0; mt < 2; mt++) {
                    float x00 = fmaxf(acc[mt][nt][0] + bb0, 0.f);
                    float x01 = fmaxf(acc[mt][nt][1] + bb1, 0.f);
                    float x10 = fmaxf(acc[mt][nt][2] + bb0, 0.f);
                    float x11 = fmaxf(acc[mt][nt][3] + bb1, 0.f);
                    p[mt][0][0] = fmaf(x00, w300, fmaf(x01, w301, p[mt][0][0]));
                    p[mt][0][1] = fmaf(x00, w310, fmaf(x01, w311, p[mt][0][1]));
                    p[mt][1][0] = fmaf(x10, w300, fmaf(x11, w301, p[mt][1][0]));
                    p[mt][1][1] = fmaf(x10, w310, fmaf(x11, w311, p[mt][1][1]));
                }
            }

            #pragma unroll
            for (int mt = 0; mt < 2; mt++)
                #pragma unroll
                for (int r = 0; r < 2; r++)
                    #pragma unroll
                    for (int o = 0; o < 2; o++) {
                        float v = p[mt][r][o];
                        v += __shfl_xor_sync(0xffffffffu, v, 1);
                        v += __shfl_xor_sync(0xffffffffu, v, 2);
                        p[mt][r][o] = v;
                    }

            if (tig == 0) {
                #pragma unroll
                for (int mt = 0; mt < 2; mt++) {
                    int r0 = wm * 32 + mt * 16 + g;
                    s_part[wn][r0][0]     = p[mt][0][0];
                    s_part[wn][r0][1]     = p[mt][0][1];
                    s_part[wn][r0 + 8][0] = p[mt][1][0];
                    s_part[wn][r0 + 8][1] = p[mt][1][1];
                }
            }
            asm volatile("bar.sync 1, 256;" ::: "memory");
            // 256 consumer threads write 128 edges x 2 outputs
            out[(size_t)t * 256 + tid] =
                s_part[0][tid >> 1][tid & 1] + s_part[1][tid >> 1][tid & 1] + s_b3[tid & 1];
        } else {
            int tn = t + EDGE_GRID;
            if (tn < TILES) fill(buf ^ 1, tn);
        }
        __syncthreads();
    }
}

// ---------------------------------------------------------------------------
extern "C" void kernel_launch(void* const* d_in, const int* in_sizes, int n_in,
                              void* d_out, int out_size) {
    const float* h   = (const float*)d_in[0];
    const int*   src = (const int*)d_in[1];
    const int*   dst = (const int*)d_in[2];
    const float* W1  = (const float*)d_in[3];
    const float* b1  = (const float*)d_in[4];
    const float* W2  = (const float*)d_in[5];
    const float* b2  = (const float*)d_in[6];
    const float* W3  = (const float*)d_in[7];
    const float* b3  = (const float*)d_in[8];
    float* out = (float*)d_out;

    const int edge_smem = 6 * TSZ * (int)sizeof(__nv_bfloat16);  // 208896
    cudaFuncSetAttribute(node_kernel, cudaFuncAttributeMaxDynamicSharedMemorySize, 98304);
    cudaFuncSetAttribute(edge_kernel, cudaFuncAttributeMaxDynamicSharedMemorySize, edge_smem);

    dim3 g1((N_NODES + 63) / 64, 2);
    node_kernel<<<g1, 256, 98304>>>(h, W1, b1);
    edge_kernel<<<EDGE_GRID, 384, edge_smem>>>(src, dst, W2, b2, W3, b3, out);
}

// round 5
// speedup vs baseline: 4.7997x; 1.4674x over previous
#include <cuda_runtime.h>
#include <cuda_bf16.h>
#include <cstdint>

#define N_NODES 100000
#define N_EDGES 800000
#define F 128
#define HID 128
#define PITCH 136            // bf16 per row in shared tiles (conflict-free frag loads)
#define TSZ (128 * PITCH)    // one 128-row tile in bf16 elems
#define TILES (N_EDGES / 128)
#define NT_TILES ((N_NODES + 127) / 128)
#define EDGE_GRID 148

// Precomputed per-node tables: A = h @ W1[0:128,:] + b1,  B = h @ W1[128:256,:]
__device__ float d_AB[2u * N_NODES * F];

// ---------------------------------------------------------------------------
__device__ __forceinline__ void mma_bf16(float* c, const uint32_t* a, const uint32_t* b) {
    asm volatile(
        "mma.sync.aligned.m16n8k16.row.col.f32.bf16.bf16.f32 "
        "{%0,%1,%2,%3}, {%4,%5,%6,%7}, {%8,%9}, {%0,%1,%2,%3};\n"
        : "+f"(c[0]), "+f"(c[1]), "+f"(c[2]), "+f"(c[3])
        : "r"(a[0]), "r"(a[1]), "r"(a[2]), "r"(a[3]), "r"(b[0]), "r"(b[1]));
}

__device__ __forceinline__ void split_bf16(float x, __nv_bfloat16& hi, __nv_bfloat16& lo) {
    hi = __float2bfloat16(x);
    lo = __float2bfloat16(x - __bfloat162float(hi));
}

__device__ __forceinline__ uint32_t pack2(__nv_bfloat16 a, __nv_bfloat16 b) {
    __nv_bfloat162 t = __halves2bfloat162(a, b);
    return *(uint32_t*)&t;
}

// ---------------------------------------------------------------------------
// Kernel 1: node GEMM, tensor-core, persistent + warp-specialized.
// grid (148, 2): y = part. Producers stream h rows, consumers 3-pass bf16 MMA
// against the part's W1 slice; epilogue stores 128x128 fp32 tile to d_AB.
// ---------------------------------------------------------------------------
__global__ void __launch_bounds__(384, 1)
node_kernel(const float* __restrict__ h,
            const float* __restrict__ W1,
            const float* __restrict__ b1) {
    extern __shared__ __nv_bfloat16 smb[];
    __nv_bfloat16* w_hi = smb;                 // [n][k] transposed, this part's slice
    __nv_bfloat16* w_lo = smb + TSZ;
    __nv_bfloat16* xbuf = smb + 2 * TSZ;       // double buffer {hi,lo}

    __shared__ float s_b1[128];

    const int tid  = threadIdx.x;
    const int lane = tid & 31;
    const int part = blockIdx.y;

    // one-time: W1 slice split (transposed)
    const float* Wp = W1 + part * F * HID;
    for (int idx = tid; idx < 128 * 128; idx += 384) {
        int k = idx >> 7, n = idx & 127;
        float w = Wp[idx];
        __nv_bfloat16 wh, wl;
        split_bf16(w, wh, wl);
        w_hi[n * PITCH + k] = wh;
        w_lo[n * PITCH + k] = wl;
    }
    if (tid < 128) s_b1[tid] = (part == 0) ? b1[tid] : 0.f;
    __syncthreads();

    const bool is_consumer = tid < 256;
    const int  ptid = tid - 256;

    const float4* h4 = (const float4*)h;
    auto fill = [&](int buf, int t) {
        __nv_bfloat16* xh = xbuf + (2 * buf) * TSZ;
        __nv_bfloat16* xl = xbuf + (2 * buf + 1) * TSZ;
        const int r0 = t * 128;
        #pragma unroll
        for (int i = 0; i < 32; i++) {
            int lin = ptid + 128 * i;
            int e = lin >> 5, v = lin & 31;
            int r = r0 + e;
            float4 a = make_float4(0.f, 0.f, 0.f, 0.f);
            if (r < N_NODES) a = h4[(size_t)r * 32 + v];
            __nv_bfloat16 h0, h1, h2, h3, l0, l1, l2, l3;
            split_bf16(a.x, h0, l0); split_bf16(a.y, h1, l1);
            split_bf16(a.z, h2, l2); split_bf16(a.w, h3, l3);
            int base = e * PITCH + v * 4;
            *(uint2*)&xh[base] = make_uint2(pack2(h0, h1), pack2(h2, h3));
            *(uint2*)&xl[base] = make_uint2(pack2(l0, l1), pack2(l2, l3));
        }
    };

    if (!is_consumer) fill(0, blockIdx.x);
    __syncthreads();

    const int warp = tid >> 5;
    const int g    = lane >> 2;
    const int tig  = lane & 3;
    const int wm   = warp & 3;
    const int wn   = warp >> 2;

    float* table = d_AB + (size_t)part * N_NODES * F;

    int s = 0;
    for (int t = blockIdx.x; t < NT_TILES; t += EDGE_GRID, s++) {
        const int buf = s & 1;
        if (is_consumer) {
            const __nv_bfloat16* xh = xbuf + (2 * buf) * TSZ;
            const __nv_bfloat16* xl = xbuf + (2 * buf + 1) * TSZ;

            float acc[2][8][4];
            #pragma unroll
            for (int mt = 0; mt < 2; mt++)
                #pragma unroll
                for (int nt = 0; nt < 8; nt++)
                    #pragma unroll
                    for (int q = 0; q < 4; q++) acc[mt][nt][q] = 0.f;

            #pragma unroll
            for (int ks = 0; ks < 8; ks++) {
                const int ka = ks * 16 + 2 * tig;

                uint32_t a_hi[2][4], a_lo[2][4];
                #pragma unroll
                for (int mt = 0; mt < 2; mt++) {
                    int m = wm * 32 + mt * 16 + g;
                    const __nv_bfloat16* ph = &xh[m * PITCH + ka];
                    const __nv_bfloat16* pl = &xl[m * PITCH + ka];
                    a_hi[mt][0] = *(const uint32_t*)ph;
                    a_hi[mt][1] = *(const uint32_t*)(ph + 8 * PITCH);
                    a_hi[mt][2] = *(const uint32_t*)(ph + 8);
                    a_hi[mt][3] = *(const uint32_t*)(ph + 8 * PITCH + 8);
                    a_lo[mt][0] = *(const uint32_t*)pl;
                    a_lo[mt][1] = *(const uint32_t*)(pl + 8 * PITCH);
                    a_lo[mt][2] = *(const uint32_t*)(pl + 8);
                    a_lo[mt][3] = *(const uint32_t*)(pl + 8 * PITCH + 8);
                }

                uint32_t b_hi[8][2], b_lo[8][2];
                #pragma unroll
                for (int nt = 0; nt < 8; nt++) {
                    int n = wn * 64 + nt * 8 + g;
                    const __nv_bfloat16* pw = &w_hi[n * PITCH + ka];
                    const __nv_bfloat16* pv = &w_lo[n * PITCH + ka];
                    b_hi[nt][0] = *(const uint32_t*)pw;
                    b_hi[nt][1] = *(const uint32_t*)(pw + 8);
                    b_lo[nt][0] = *(const uint32_t*)pv;
                    b_lo[nt][1] = *(const uint32_t*)(pv + 8);
                }

                #pragma unroll
                for (int mt = 0; mt < 2; mt++)
                    #pragma unroll
                    for (int nt = 0; nt < 8; nt++) {
                        mma_bf16(acc[mt][nt], a_hi[mt], b_hi[nt]);
                        mma_bf16(acc[mt][nt], a_hi[mt], b_lo[nt]);
                        mma_bf16(acc[mt][nt], a_lo[mt], b_hi[nt]);
                    }
            }

            // epilogue: +bias, store fp32 tile rows to table
            const int r_base = t * 128 + wm * 32 + g;
            #pragma unroll
            for (int mt = 0; mt < 2; mt++) {
                #pragma unroll
                for (int r = 0; r < 2; r++) {
                    int row = r_base + mt * 16 + r * 8;
                    if (row < N_NODES) {
                        float* rp = table + (size_t)row * 128 + wn * 64;
                        #pragma unroll
                        for (int nt = 0; nt < 8; nt++) {
                            int c = nt * 8 + 2 * tig;
                            float2 v;
                            v.x = acc[mt][nt][2 * r]     + s_b1[wn * 64 + c];
                            v.y = acc[mt][nt][2 * r + 1] + s_b1[wn * 64 + c + 1];
                            *(float2*)(rp + c) = v;
                        }
                    }
                }
            }
        } else {
            int tn = t + EDGE_GRID;
            if (tn < NT_TILES) fill(buf ^ 1, tn);
        }
        __syncthreads();
    }
}

// ---------------------------------------------------------------------------
// Kernel 2: persistent, warp-specialized edge kernel (unchanged from R4).
// ---------------------------------------------------------------------------
__global__ void __launch_bounds__(384, 1)
edge_kernel(const int* __restrict__ src,
            const int* __restrict__ dst,
            const float* __restrict__ W2,
            const float* __restrict__ b2,
            const float* __restrict__ W3,
            const float* __restrict__ b3,
            float* __restrict__ out) {
    extern __shared__ __nv_bfloat16 smb[];
    __nv_bfloat16* w_hi = smb;
    __nv_bfloat16* w_lo = smb + TSZ;
    __nv_bfloat16* xbuf = smb + 2 * TSZ;

    __shared__ float s_b2[128];
    __shared__ float s_w3[256];
    __shared__ float s_b3[2];
    __shared__ float s_part[2][128][2];

    const int tid  = threadIdx.x;
    const int lane = tid & 31;

    for (int idx = tid; idx < 128 * 128; idx += 384) {
        int k = idx >> 7, n = idx & 127;
        float w = W2[idx];
        __nv_bfloat16 wh, wl;
        split_bf16(w, wh, wl);
        w_hi[n * PITCH + k] = wh;
        w_lo[n * PITCH + k] = wl;
    }
    if (tid < 128) s_b2[tid] = b2[tid];
    if (tid < 256) s_w3[tid] = W3[tid];
    if (tid < 2)   s_b3[tid] = b3[tid];
    __syncthreads();

    const float4* A4 = (const float4*)d_AB;
    const float4* B4 = (const float4*)(d_AB + (size_t)N_NODES * F);
    const bool is_consumer = tid < 256;
    const int  ptid = tid - 256;

    auto fill = [&](int buf, int t) {
        __nv_bfloat16* xh = xbuf + (2 * buf) * TSZ;
        __nv_bfloat16* xl = xbuf + (2 * buf + 1) * TSZ;
        const int e0 = t * 128;
        #pragma unroll
        for (int i = 0; i < 32; i++) {
            int lin = ptid + 128 * i;
            int e = lin >> 5, v = lin & 31;
            int si = src[e0 + e], di = dst[e0 + e];
            float4 a = A4[(size_t)si * 32 + v];
            float4 b = B4[(size_t)di * 32 + v];
            float r0 = fmaxf(a.x + b.x, 0.f), r1 = fmaxf(a.y + b.y, 0.f);
            float r2 = fmaxf(a.z + b.z, 0.f), r3 = fmaxf(a.w + b.w, 0.f);
            __nv_bfloat16 h0, h1, h2, h3, l0, l1, l2, l3;
            split_bf16(r0, h0, l0); split_bf16(r1, h1, l1);
            split_bf16(r2, h2, l2); split_bf16(r3, h3, l3);
            int base = e * PITCH + v * 4;
            *(uint2*)&xh[base] = make_uint2(pack2(h0, h1), pack2(h2, h3));
            *(uint2*)&xl[base] = make_uint2(pack2(l0, l1), pack2(l2, l3));
        }
    };

    if (!is_consumer) fill(0, blockIdx.x);
    __syncthreads();

    const int warp = tid >> 5;
    const int g    = lane >> 2;
    const int tig  = lane & 3;
    const int wm   = warp & 3;
    const int wn   = warp >> 2;

    int s = 0;
    for (int t = blockIdx.x; t < TILES; t += EDGE_GRID, s++) {
        const int buf = s & 1;
        if (is_consumer) {
            const __nv_bfloat16* xh = xbuf + (2 * buf) * TSZ;
            const __nv_bfloat16* xl = xbuf + (2 * buf + 1) * TSZ;

            float acc[2][8][4];
            #pragma unroll
            for (int mt = 0; mt < 2; mt++)
                #pragma unroll
                for (int nt = 0; nt < 8; nt++)
                    #pragma unroll
                    for (int q = 0; q < 4; q++) acc[mt][nt][q] = 0.f;

            #pragma unroll
            for (int ks = 0; ks < 8; ks++) {
                const int ka = ks * 16 + 2 * tig;

                uint32_t a_hi[2][4], a_lo[2][4];
                #pragma unroll
                for (int mt = 0; mt < 2; mt++) {
                    int m = wm * 32 + mt * 16 + g;
                    const __nv_bfloat16* ph = &xh[m * PITCH + ka];
                    const __nv_bfloat16* pl = &xl[m * PITCH + ka];
                    a_hi[mt][0] = *(const uint32_t*)ph;
                    a_hi[mt][1] = *(const uint32_t*)(ph + 8 * PITCH);
                    a_hi[mt][2] = *(const uint32_t*)(ph + 8);
                    a_hi[mt][3] = *(const uint32_t*)(ph + 8 * PITCH + 8);
                    a_lo[mt][0] = *(const uint32_t*)pl;
                    a_lo[mt][1] = *(const uint32_t*)(pl + 8 * PITCH);
                    a_lo[mt][2] = *(const uint32_t*)(pl + 8);
                    a_lo[mt][3] = *(const uint32_t*)(pl + 8 * PITCH + 8);
                }

                uint32_t b_hi[8][2], b_lo[8][2];
                #pragma unroll
                for (int nt = 0; nt < 8; nt++) {
                    int n = wn * 64 + nt * 8 + g;
                    const __nv_bfloat16* pw = &w_hi[n * PITCH + ka];
                    const __nv_bfloat16* pv = &w_lo[n * PITCH + ka];
                    b_hi[nt][0] = *(const uint32_t*)pw;
                    b_hi[nt][1] = *(const uint32_t*)(pw + 8);
                    b_lo[nt][0] = *(const uint32_t*)pv;
                    b_lo[nt][1] = *(const uint32_t*)(pv + 8);
                }

                #pragma unroll
                for (int mt = 0; mt < 2; mt++)
                    #pragma unroll
                    for (int nt = 0; nt < 8; nt++) {
                        mma_bf16(acc[mt][nt], a_hi[mt], b_hi[nt]);
                        mma_bf16(acc[mt][nt], a_hi[mt], b_lo[nt]);
                        mma_bf16(acc[mt][nt], a_lo[mt], b_hi[nt]);
                    }
            }

            float p[2][2][2];
            #pragma unroll
            for (int mt = 0; mt < 2; mt++)
                #pragma unroll
                for (int r = 0; r < 2; r++) { p[mt][r][0] = 0.f; p[mt][r][1] = 0.f; }

            #pragma unroll
            for (int nt = 0; nt < 8; nt++) {
                int c0 = wn * 64 + nt * 8 + 2 * tig;
                float bb0 = s_b2[c0], bb1 = s_b2[c0 + 1];
                float w300 = s_w3[c0 * 2],       w310 = s_w3[c0 * 2 + 1];
                float w301 = s_w3[(c0 + 1) * 2], w311 = s_w3[(c0 + 1) * 2 + 1];
                #pragma unroll
                for (int mt = 0; mt < 2; mt++) {
                    float x00 = fmaxf(acc[mt][nt][0] + bb0, 0.f);
                    float x01 = fmaxf(acc[mt][nt][1] + bb1, 0.f);
                    float x10 = fmaxf(acc[mt][nt][2] + bb0, 0.f);
                    float x11 = fmaxf(acc[mt][nt][3] + bb1, 0.f);
                    p[mt][0][0] = fmaf(x00, w300, fmaf(x01, w301, p[mt][0][0]));
                    p[mt][0][1] = fmaf(x00, w310, fmaf(x01, w311, p[mt][0][1]));
                    p[mt][1][0] = fmaf(x10, w300, fmaf(x11, w301, p[mt][1][0]));
                    p[mt][1][1] = fmaf(x10, w310, fmaf(x11, w311, p[mt][1][1]));
                }
            }

            #pragma unroll
            for (int mt = 0; mt < 2; mt++)
                #pragma unroll
                for (int r = 0; r < 2; r++)
                    #pragma unroll
                    for (int o = 0; o < 2; o++) {
                        float v = p[mt][r][o];
                        v += __shfl_xor_sync(0xffffffffu, v, 1);
                        v += __shfl_xor_sync(0xffffffffu, v, 2);
                        p[mt][r][o] = v;
                    }

            if (tig == 0) {
                #pragma unroll
                for (int mt = 0; mt < 2; mt++) {
                    int r0 = wm * 32 + mt * 16 + g;
                    s_part[wn][r0][0]     = p[mt][0][0];
                    s_part[wn][r0][1]     = p[mt][0][1];
                    s_part[wn][r0 + 8][0] = p[mt][1][0];
                    s_part[wn][r0 + 8][1] = p[mt][1][1];
                }
            }
            asm volatile("bar.sync 1, 256;" ::: "memory");
            out[(size_t)t * 256 + tid] =
                s_part[0][tid >> 1][tid & 1] + s_part[1][tid >> 1][tid & 1] + s_b3[tid & 1];
        } else {
            int tn = t + EDGE_GRID;
            if (tn < TILES) fill(buf ^ 1, tn);
        }
        __syncthreads();
    }
}

// ---------------------------------------------------------------------------
extern "C" void kernel_launch(void* const* d_in, const int* in_sizes, int n_in,
                              void* d_out, int out_size) {
    const float* h   = (const float*)d_in[0];
    const int*   src = (const int*)d_in[1];
    const int*   dst = (const int*)d_in[2];
    const float* W1  = (const float*)d_in[3];
    const float* b1  = (const float*)d_in[4];
    const float* W2  = (const float*)d_in[5];
    const float* b2  = (const float*)d_in[6];
    const float* W3  = (const float*)d_in[7];
    const float* b3  = (const float*)d_in[8];
    float* out = (float*)d_out;

    const int smem = 6 * TSZ * (int)sizeof(__nv_bfloat16);  // 208896
    cudaFuncSetAttribute(node_kernel, cudaFuncAttributeMaxDynamicSharedMemorySize, smem);
    cudaFuncSetAttribute(edge_kernel, cudaFuncAttributeMaxDynamicSharedMemorySize, smem);

    node_kernel<<<dim3(EDGE_GRID, 2), 384, smem>>>(h, W1, b1);
    edge_kernel<<<EDGE_GRID, 384, smem>>>(src, dst, W2, b2, W3, b3, out);
}

// round 7
// speedup vs baseline: 5.3823x; 1.1214x over previous
#include <cuda_runtime.h>
#include <cuda_bf16.h>
#include <cstdint>

#define N_NODES 100000
#define N_EDGES 800000
#define F 128
#define HID 128
#define PITCH 136            // bf16 per row in shared tiles (conflict-free LDSM)
#define TSZ (128 * PITCH)
#define TILES (N_EDGES / 128)
#define NT_TILES ((N_NODES + 127) / 128)
#define GRID 148

// Precomputed per-node tables: A = h @ W1[0:128,:] + b1,  B = h @ W1[128:256,:]
__device__ float d_AB[2u * N_NODES * F];

// ---------------------------------------------------------------------------
__device__ __forceinline__ void mma_bf16(float* c, const uint32_t* a, const uint32_t* b) {
    asm volatile(
        "mma.sync.aligned.m16n8k16.row.col.f32.bf16.bf16.f32 "
        "{%0,%1,%2,%3}, {%4,%5,%6,%7}, {%8,%9}, {%0,%1,%2,%3};\n"
        : "+f"(c[0]), "+f"(c[1]), "+f"(c[2]), "+f"(c[3])
        : "r"(a[0]), "r"(a[1]), "r"(a[2]), "r"(a[3]), "r"(b[0]), "r"(b[1]));
}

__device__ __forceinline__ void ldsm4(uint32_t* r, uint32_t addr) {
    asm volatile("ldmatrix.sync.aligned.m8n8.x4.shared.b16 {%0,%1,%2,%3}, [%4];"
                 : "=r"(r[0]), "=r"(r[1]), "=r"(r[2]), "=r"(r[3]) : "r"(addr));
}

__device__ __forceinline__ void split_bf16(float x, __nv_bfloat16& hi, __nv_bfloat16& lo) {
    hi = __float2bfloat16(x);
    lo = __float2bfloat16(x - __bfloat162float(hi));
}

__device__ __forceinline__ uint32_t pack2(__nv_bfloat16 a, __nv_bfloat16 b) {
    __nv_bfloat162 t = __halves2bfloat162(a, b);
    return *(uint32_t*)&t;
}

__device__ __forceinline__ uint32_t smem_u32(const void* p) {
    uint32_t a;
    asm("{ .reg .u64 t; cvta.to.shared.u64 t, %1; cvt.u32.u64 %0, t; }" : "=r"(a) : "l"(p));
    return a;
}

// Per-lane LDSM byte offsets within a [row][PITCH] bf16 tile.
// A (x4: rows 0-15, k 0-7 / 8-15): row = lane&15, +8 k-cols for lanes 16-31.
__device__ __forceinline__ uint32_t ldsmA_off(int lane) {
    return (uint32_t)(((lane & 15) * PITCH + ((lane >> 4) * 8)) * 2);
}
// B (x4: two n-groups of 8, k 0-7 / 8-15): n = (lane&7) + ((lane&16)>>1), k+8 for lanes 8-15/24-31.
__device__ __forceinline__ uint32_t ldsmB_off(int lane) {
    return (uint32_t)((((lane & 7) + ((lane & 16) >> 1)) * PITCH + ((lane & 8) ? 8 : 0)) * 2);
}

// ---------------------------------------------------------------------------
// Kernel 1: node GEMM — persistent, warp-specialized, 3-pass bf16-split mma.sync.
// grid (148, 2): y = part (A / B table).
// ---------------------------------------------------------------------------
__global__ void __launch_bounds__(384, 1)
node_kernel(const float* __restrict__ h,
            const float* __restrict__ W1,
            const float* __restrict__ b1) {
    extern __shared__ __nv_bfloat16 smb[];
    __nv_bfloat16* w_hi = smb;
    __nv_bfloat16* w_lo = smb + TSZ;
    __nv_bfloat16* xbuf = smb + 2 * TSZ;

    __shared__ float s_b1[128];

    const int tid  = threadIdx.x;
    const int lane = tid & 31;
    const int part = blockIdx.y;

    const float* Wp = W1 + part * F * HID;
    for (int idx = tid; idx < 128 * 128; idx += 384) {
        int k = idx >> 7, n = idx & 127;
        float w = Wp[idx];
        __nv_bfloat16 wh, wl;
        split_bf16(w, wh, wl);
        w_hi[n * PITCH + k] = wh;
        w_lo[n * PITCH + k] = wl;
    }
    if (tid < 128) s_b1[tid] = (part == 0) ? b1[tid] : 0.f;
    __syncthreads();

    const bool is_consumer = tid < 256;
    const int  ptid = tid - 256;

    const float4* h4 = (const float4*)h;
    auto fill = [&](int buf, int t) {
        __nv_bfloat16* xh = xbuf + (2 * buf) * TSZ;
        __nv_bfloat16* xl = xbuf + (2 * buf + 1) * TSZ;
        const int r0 = t * 128;
        #pragma unroll
        for (int i = 0; i < 32; i++) {
            int lin = ptid + 128 * i;
            int e = lin >> 5, v = lin & 31;
            int r = r0 + e;
            float4 a = make_float4(0.f, 0.f, 0.f, 0.f);
            if (r < N_NODES) a = h4[(size_t)r * 32 + v];
            __nv_bfloat16 h0, h1, h2, h3, l0, l1, l2, l3;
            split_bf16(a.x, h0, l0); split_bf16(a.y, h1, l1);
            split_bf16(a.z, h2, l2); split_bf16(a.w, h3, l3);
            int base = e * PITCH + v * 4;
            *(uint2*)&xh[base] = make_uint2(pack2(h0, h1), pack2(h2, h3));
            *(uint2*)&xl[base] = make_uint2(pack2(l0, l1), pack2(l2, l3));
        }
    };

    if (!is_consumer) fill(0, blockIdx.x);
    __syncthreads();

    const int warp = tid >> 5;
    const int g    = lane >> 2;
    const int tig  = lane & 3;
    const int wm   = warp & 3;
    const int wn   = warp >> 2;

    // LDSM lane offsets (bytes), warp-tile bases included
    const uint32_t offA = ldsmA_off(lane) + (uint32_t)(wm * 32 * PITCH * 2);
    const uint32_t offB = ldsmB_off(lane) + (uint32_t)(wn * 64 * PITCH * 2);
    const uint32_t wh_a = smem_u32(w_hi) + offB;
    const uint32_t wl_a = smem_u32(w_lo) + offB;

    float* table = d_AB + (size_t)part * N_NODES * F;

    int s = 0;
    for (int t = blockIdx.x; t < NT_TILES; t += GRID, s++) {
        const int buf = s & 1;
        if (is_consumer) {
            const uint32_t xh_a = smem_u32(xbuf + (2 * buf) * TSZ) + offA;
            const uint32_t xl_a = smem_u32(xbuf + (2 * buf + 1) * TSZ) + offA;

            float acc[2][8][4];
            #pragma unroll
            for (int mt = 0; mt < 2; mt++)
                #pragma unroll
                for (int nt = 0; nt < 8; nt++)
                    #pragma unroll
                    for (int q = 0; q < 4; q++) acc[mt][nt][q] = 0.f;

            #pragma unroll
            for (int ks = 0; ks < 8; ks++) {
                const uint32_t kb = ks * 32;   // 16 bf16 = 32 bytes

                uint32_t a_hi[2][4], a_lo[2][4];
                #pragma unroll
                for (int mt = 0; mt < 2; mt++) {
                    ldsm4(a_hi[mt], xh_a + mt * (16 * PITCH * 2) + kb);
                    ldsm4(a_lo[mt], xl_a + mt * (16 * PITCH * 2) + kb);
                }

                uint32_t b_hi[8][2], b_lo[8][2];
                #pragma unroll
                for (int np = 0; np < 4; np++) {
                    ldsm4(&b_hi[2 * np][0], wh_a + np * (16 * PITCH * 2) + kb);
                    ldsm4(&b_lo[2 * np][0], wl_a + np * (16 * PITCH * 2) + kb);
                }

                #pragma unroll
                for (int mt = 0; mt < 2; mt++)
                    #pragma unroll
                    for (int nt = 0; nt < 8; nt++) {
                        mma_bf16(acc[mt][nt], a_hi[mt], b_hi[nt]);
                        mma_bf16(acc[mt][nt], a_hi[mt], b_lo[nt]);
                        mma_bf16(acc[mt][nt], a_lo[mt], b_hi[nt]);
                    }
            }

            const int r_base = t * 128 + wm * 32 + g;
            #pragma unroll
            for (int mt = 0; mt < 2; mt++) {
                #pragma unroll
                for (int r = 0; r < 2; r++) {
                    int row = r_base + mt * 16 + r * 8;
                    if (row < N_NODES) {
                        float* rp = table + (size_t)row * 128 + wn * 64;
                        #pragma unroll
                        for (int nt = 0; nt < 8; nt++) {
                            int c = nt * 8 + 2 * tig;
                            float2 v;
                            v.x = acc[mt][nt][2 * r]     + s_b1[wn * 64 + c];
                            v.y = acc[mt][nt][2 * r + 1] + s_b1[wn * 64 + c + 1];
                            *(float2*)(rp + c) = v;
                        }
                    }
                }
            }
        } else {
            int tn = t + GRID;
            if (tn < NT_TILES) fill(buf ^ 1, tn);
        }
        __syncthreads();
    }
}

// ---------------------------------------------------------------------------
// Kernel 2: edge kernel — persistent, warp-specialized, LDSM + mma.sync.
// ---------------------------------------------------------------------------
__global__ void __launch_bounds__(384, 1)
edge_kernel(const int* __restrict__ src,
            const int* __restrict__ dst,
            const float* __restrict__ W2,
            const float* __restrict__ b2,
            const float* __restrict__ W3,
            const float* __restrict__ b3,
            float* __restrict__ out) {
    extern __shared__ __nv_bfloat16 smb[];
    __nv_bfloat16* w_hi = smb;
    __nv_bfloat16* w_lo = smb + TSZ;
    __nv_bfloat16* xbuf = smb + 2 * TSZ;

    __shared__ float s_b2[128];
    __shared__ float s_w3[256];
    __shared__ float s_b3[2];
    __shared__ float s_part[2][128][2];

    const int tid  = threadIdx.x;
    const int lane = tid & 31;

    for (int idx = tid; idx < 128 * 128; idx += 384) {
        int k = idx >> 7, n = idx & 127;
        float w = W2[idx];
        __nv_bfloat16 wh, wl;
        split_bf16(w, wh, wl);
        w_hi[n * PITCH + k] = wh;
        w_lo[n * PITCH + k] = wl;
    }
    if (tid < 128) s_b2[tid] = b2[tid];
    if (tid < 256) s_w3[tid] = W3[tid];
    if (tid < 2)   s_b3[tid] = b3[tid];
    __syncthreads();

    const float4* A4 = (const float4*)d_AB;
    const float4* B4 = (const float4*)(d_AB + (size_t)N_NODES * F);
    const bool is_consumer = tid < 256;
    const int  ptid = tid - 256;

    auto fill = [&](int buf, int t) {
        __nv_bfloat16* xh = xbuf + (2 * buf) * TSZ;
        __nv_bfloat16* xl = xbuf + (2 * buf + 1) * TSZ;
        const int e0 = t * 128;
        #pragma unroll
        for (int i = 0; i < 32; i++) {
            int lin = ptid + 128 * i;
            int e = lin >> 5, v = lin & 31;
            int si = src[e0 + e], di = dst[e0 + e];
            float4 a = A4[(size_t)si * 32 + v];
            float4 b = B4[(size_t)di * 32 + v];
            float r0 = fmaxf(a.x + b.x, 0.f), r1 = fmaxf(a.y + b.y, 0.f);
            float r2 = fmaxf(a.z + b.z, 0.f), r3 = fmaxf(a.w + b.w, 0.f);
            __nv_bfloat16 h0, h1, h2, h3, l0, l1, l2, l3;
            split_bf16(r0, h0, l0); split_bf16(r1, h1, l1);
            split_bf16(r2, h2, l2); split_bf16(r3, h3, l3);
            int base = e * PITCH + v * 4;
            *(uint2*)&xh[base] = make_uint2(pack2(h0, h1), pack2(h2, h3));
            *(uint2*)&xl[base] = make_uint2(pack2(l0, l1), pack2(l2, l3));
        }
    };

    if (!is_consumer) fill(0, blockIdx.x);
    __syncthreads();

    const int warp = tid >> 5;
    const int g    = lane >> 2;
    const int tig  = lane & 3;
    const int wm   = warp & 3;
    const int wn   = warp >> 2;

    const uint32_t offA = ldsmA_off(lane) + (uint32_t)(wm * 32 * PITCH * 2);
    const uint32_t offB = ldsmB_off(lane) + (uint32_t)(wn * 64 * PITCH * 2);
    const uint32_t wh_a = smem_u32(w_hi) + offB;
    const uint32_t wl_a = smem_u32(w_lo) + offB;

    int s = 0;
    for (int t = blockIdx.x; t < TILES; t += GRID, s++) {
        const int buf = s & 1;
        if (is_consumer) {
            const uint32_t xh_a = smem_u32(xbuf + (2 * buf) * TSZ) + offA;
            const uint32_t xl_a = smem_u32(xbuf + (2 * buf + 1) * TSZ) + offA;

            float acc[2][8][4];
            #pragma unroll
            for (int mt = 0; mt < 2; mt++)
                #pragma unroll
                for (int nt = 0; nt < 8; nt++)
                    #pragma unroll
                    for (int q = 0; q < 4; q++) acc[mt][nt][q] = 0.f;

            #pragma unroll
            for (int ks = 0; ks < 8; ks++) {
                const uint32_t kb = ks * 32;

                uint32_t a_hi[2][4], a_lo[2][4];
                #pragma unroll
                for (int mt = 0; mt < 2; mt++) {
                    ldsm4(a_hi[mt], xh_a + mt * (16 * PITCH * 2) + kb);
                    ldsm4(a_lo[mt], xl_a + mt * (16 * PITCH * 2) + kb);
                }

                uint32_t b_hi[8][2], b_lo[8][2];
                #pragma unroll
                for (int np = 0; np < 4; np++) {
                    ldsm4(&b_hi[2 * np][0], wh_a + np * (16 * PITCH * 2) + kb);
                    ldsm4(&b_lo[2 * np][0], wl_a + np * (16 * PITCH * 2) + kb);
                }

                #pragma unroll
                for (int mt = 0; mt < 2; mt++)
                    #pragma unroll
                    for (int nt = 0; nt < 8; nt++) {
                        mma_bf16(acc[mt][nt], a_hi[mt], b_hi[nt]);
                        mma_bf16(acc[mt][nt], a_hi[mt], b_lo[nt]);
                        mma_bf16(acc[mt][nt], a_lo[mt], b_hi[nt]);
                    }
            }

            float p[2][2][2];
            #pragma unroll
            for (int mt = 0; mt < 2; mt++)
                #pragma unroll
                for (int r = 0; r < 2; r++) { p[mt][r][0] = 0.f; p[mt][r][1] = 0.f; }

            #pragma unroll
            for (int nt = 0; nt < 8; nt++) {
                int c0 = wn * 64 + nt * 8 + 2 * tig;
                float bb0 = s_b2[c0], bb1 = s_b2[c0 + 1];
                float w300 = s_w3[c0 * 2],       w310 = s_w3[c0 * 2 + 1];
                float w301 = s_w3[(c0 + 1) * 2], w311 = s_w3[(c0 + 1) * 2 + 1];
                #pragma unroll
                for (int mt = 0; mt < 2; mt++) {
                    float x00 = fmaxf(acc[mt][nt][0] + bb0, 0.f);
                    float x01 = fmaxf(acc[mt][nt][1] + bb1, 0.f);
                    float x10 = fmaxf(acc[mt][nt][2] + bb0, 0.f);
                    float x11 = fmaxf(acc[mt][nt][3] + bb1, 0.f);
                    p[mt][0][0] = fmaf(x00, w300, fmaf(x01, w301, p[mt][0][0]));
                    p[mt][0][1] = fmaf(x00, w310, fmaf(x01, w311, p[mt][0][1]));
                    p[mt][1][0] = fmaf(x10, w300, fmaf(x11, w301, p[mt][1][0]));
                    p[mt][1][1] = fmaf(x10, w310, fmaf(x11, w311, p[mt][1][1]));
                }
            }

            #pragma unroll
            for (int mt = 0; mt < 2; mt++)
                #pragma unroll
                for (int r = 0; r < 2; r++)
                    #pragma unroll
                    for (int o = 0; o < 2; o++) {
                        float v = p[mt][r][o];
                        v += __shfl_xor_sync(0xffffffffu, v, 1);
                        v += __shfl_xor_sync(0xffffffffu, v, 2);
                        p[mt][r][o] = v;
                    }

            if (tig == 0) {
                #pragma unroll
                for (int mt = 0; mt < 2; mt++) {
                    int r0 = wm * 32 + mt * 16 + g;
                    s_part[wn][r0][0]     = p[mt][0][0];
                    s_part[wn][r0][1]     = p[mt][0][1];
                    s_part[wn][r0 + 8][0] = p[mt][1][0];
                    s_part[wn][r0 + 8][1] = p[mt][1][1];
                }
            }
            asm volatile("bar.sync 1, 256;" ::: "memory");
            out[(size_t)t * 256 + tid] =
                s_part[0][tid >> 1][tid & 1] + s_part[1][tid >> 1][tid & 1] + s_b3[tid & 1];
        } else {
            int tn = t + GRID;
            if (tn < TILES) fill(buf ^ 1, tn);
        }
        __syncthreads();
    }
}

// ---------------------------------------------------------------------------
extern "C" void kernel_launch(void* const* d_in, const int* in_sizes, int n_in,
                              void* d_out, int out_size) {
    const float* h   = (const float*)d_in[0];
    const int*   src = (const int*)d_in[1];
    const int*   dst = (const int*)d_in[2];
    const float* W1  = (const float*)d_in[3];
    const float* b1  = (const float*)d_in[4];
    const float* W2  = (const float*)d_in[5];
    const float* b2  = (const float*)d_in[6];
    const float* W3  = (const float*)d_in[7];
    const float* b3  = (const float*)d_in[8];
    float* out = (float*)d_out;

    const int smem = 6 * TSZ * (int)sizeof(__nv_bfloat16);  // 208896
    cudaFuncSetAttribute(node_kernel, cudaFuncAttributeMaxDynamicSharedMemorySize, smem);
    cudaFuncSetAttribute(edge_kernel, cudaFuncAttributeMaxDynamicSharedMemorySize, smem);

    node_kernel<<<dim3(GRID, 2), 384, smem>>>(h, W1, b1);
    edge_kernel<<<GRID, 384, smem>>>(src, dst, W2, b2, W3, b3, out);
}